// round 6
// baseline (speedup 1.0000x reference)
#include <cuda_runtime.h>
#include <cuda_bf16.h>
#include <cstdint>
#include <math.h>

#define NN 50000
#define NE 400000
#define DIN 256
#define EMB 256
#define NH 8
#define HD 32

// ---------------- scratch (device globals; no runtime alloc) ----------------
__device__ __align__(16) float    g_Pi[(size_t)NN * EMB];
__device__ __align__(16) float    g_Pj[(size_t)NN * EMB];

// CSR
__device__ int g_cnt[NN];
__device__ int g_off[NN + 1];
__device__ int g_cursor[NN];
__device__ int g_psend[NE];    // sender of perm-ordered edge

// split-bf16 operands for tensor-core GEMM
__device__ __align__(16) __nv_bfloat16 g_Ahi[(size_t)NN * DIN];
__device__ __align__(16) __nv_bfloat16 g_Alo[(size_t)NN * DIN];
__device__ __align__(16) __nv_bfloat16 g_Bhi[(size_t)512 * DIN];  // [n_global][k]
__device__ __align__(16) __nv_bfloat16 g_Blo[(size_t)512 * DIN];

// ---------------- helpers ----------------
__device__ __forceinline__ uint32_t smem_u32(const void* p) {
    uint32_t a;
    asm("{ .reg .u64 t; cvta.to.shared.u64 t, %1; cvt.u32.u64 %0, t; }" : "=r"(a) : "l"(p));
    return a;
}
__device__ __forceinline__ uint32_t sw128(uint32_t off) { return off ^ ((off >> 3) & 0x70); }

__device__ __forceinline__ void ldsm_x4(uint32_t* r, uint32_t addr) {
    asm volatile("ldmatrix.sync.aligned.m8n8.x4.shared.b16 {%0,%1,%2,%3}, [%4];"
                 : "=r"(r[0]), "=r"(r[1]), "=r"(r[2]), "=r"(r[3]) : "r"(addr));
}
__device__ __forceinline__ void mma16816(float* c, const uint32_t* a, const uint32_t* b) {
    asm volatile("mma.sync.aligned.m16n8k16.row.col.f32.bf16.bf16.f32 "
                 "{%0,%1,%2,%3}, {%4,%5,%6,%7}, {%8,%9}, {%0,%1,%2,%3};"
                 : "+f"(c[0]), "+f"(c[1]), "+f"(c[2]), "+f"(c[3])
                 : "r"(a[0]), "r"(a[1]), "r"(a[2]), "r"(a[3]), "r"(b[0]), "r"(b[1]));
}
__device__ __forceinline__ void cp_async16(uint32_t dst, const void* src) {
    asm volatile("cp.async.cg.shared.global [%0], [%1], 16;" :: "r"(dst), "l"(src));
}
#define CP_COMMIT() asm volatile("cp.async.commit_group;" ::: "memory")
#define CP_WAIT(n)  asm volatile("cp.async.wait_group %0;" :: "n"(n) : "memory")

// mish(x) = x * tanh(softplus(x)) = x * (t^2 + 2t) / (t^2 + 2t + 2),  t = e^x
__device__ __forceinline__ float mish1(float x) {
    if (x > 20.0f) return x;
    float t = __expf(x);
    float u = fmaf(t, t, t + t);
    return x * __fdividef(u, u + 2.0f);
}

// ---------------- init: zero CSR counters ----------------
__global__ void init_kernel() {
    int i = blockIdx.x * blockDim.x + threadIdx.x;
    if (i < NN) g_cnt[i] = 0;
}

// ---------------- pre-split nodes into bf16 hi/lo ----------------
__global__ __launch_bounds__(256) void presplit_nodes(const float* __restrict__ nodes) {
    size_t i = (size_t)blockIdx.x * blockDim.x + threadIdx.x;   // unit of 8 floats
    size_t total = (size_t)NN * DIN / 8;
    if (i >= total) return;
    const float4* src = (const float4*)nodes + i * 2;
    float4 v0 = src[0], v1 = src[1];
    float f[8] = {v0.x, v0.y, v0.z, v0.w, v1.x, v1.y, v1.z, v1.w};
    alignas(16) __nv_bfloat16 h[8];
    alignas(16) __nv_bfloat16 l[8];
#pragma unroll
    for (int j = 0; j < 8; j++) {
        h[j] = __float2bfloat16(f[j]);
        l[j] = __float2bfloat16(f[j] - __bfloat162float(h[j]));
    }
    *(uint4*)(g_Ahi + i * 8) = *(uint4*)h;
    *(uint4*)(g_Alo + i * 8) = *(uint4*)l;
}

// ---------------- pre-split + transpose W into [n][k] bf16 hi/lo ----------------
__global__ __launch_bounds__(256) void presplit_W(const float* __restrict__ Wi,
                                                  const float* __restrict__ Wj) {
    int idx = blockIdx.x * blockDim.x + threadIdx.x;
    if (idx >= 512 * 256) return;
    int n = idx >> 8, k = idx & 255;
    const float* W = (n < 256) ? Wi : Wj;
    int col = n & 255;
    float x = W[(size_t)k * 256 + col];
    __nv_bfloat16 h = __float2bfloat16(x);
    __nv_bfloat16 l = __float2bfloat16(x - __bfloat162float(h));
    g_Bhi[(size_t)n * 256 + k] = h;
    g_Blo[(size_t)n * 256 + k] = l;
}

// ---------------- tensor-core projection GEMM, 2-stage cp.async pipeline ----
__global__ __launch_bounds__(512) void gemm_mma(const float* __restrict__ bi,
                                                const float* __restrict__ bj) {
    extern __shared__ char dsm[];
    uint32_t base = (smem_u32(dsm) + 1023) & ~1023u;

    int tid = threadIdx.x, wid = tid >> 5, lane = tid & 31;
    int warp_m = wid & 3, warp_n = wid >> 2;
    int m_base = warp_m * 32, n_base = warp_n * 32;
    int ntile = blockIdx.x;
    int m0 = blockIdx.y * 128;
    size_t brow0 = (size_t)ntile * 128 * 256;

    float acc[2][4][4];
#pragma unroll
    for (int i = 0; i < 2; i++)
#pragma unroll
        for (int j = 0; j < 4; j++)
#pragma unroll
            for (int q = 0; q < 4; q++) acc[i][j][q] = 0.0f;

#define LOAD_STAGE(sbuf, kc_) do {                                         \
    uint32_t sAh_ = (sbuf), sAl_ = (sbuf) + 16384,                          \
             sBh_ = (sbuf) + 32768, sBl_ = (sbuf) + 49152;                  \
    int k0_ = (kc_) * 64;                                                   \
    _Pragma("unroll")                                                       \
    for (int u = tid; u < 1024; u += 512) {                                 \
        int r_ = u >> 3, g_ = u & 7;                                        \
        uint32_t off_ = sw128((uint32_t)(r_ * 128 + g_ * 16));              \
        int row_ = m0 + r_; if (row_ > NN - 1) row_ = NN - 1;               \
        size_t sa_ = (size_t)row_ * 256 + k0_ + g_ * 8;                     \
        cp_async16(sAh_ + off_, g_Ahi + sa_);                               \
        cp_async16(sAl_ + off_, g_Alo + sa_);                               \
        size_t sb_ = brow0 + (size_t)r_ * 256 + k0_ + g_ * 8;               \
        cp_async16(sBh_ + off_, g_Bhi + sb_);                               \
        cp_async16(sBl_ + off_, g_Blo + sb_);                               \
    }                                                                       \
} while (0)

    LOAD_STAGE(base, 0);
    CP_COMMIT();

    for (int kc = 0; kc < 4; kc++) {
        uint32_t cur = base + (uint32_t)(kc & 1) * 65536;
        if (kc < 3) {
            LOAD_STAGE(base + (uint32_t)((kc + 1) & 1) * 65536, kc + 1);
            CP_COMMIT();
            CP_WAIT(1);
        } else {
            CP_WAIT(0);
        }
        __syncthreads();

        uint32_t sAh = cur, sAl = cur + 16384, sBh = cur + 32768, sBl = cur + 49152;
#pragma unroll
        for (int ks = 0; ks < 4; ks++) {
            uint32_t ah[2][4], al[2][4];
#pragma unroll
            for (int mi = 0; mi < 2; mi++) {
                uint32_t off = sw128((uint32_t)((m_base + mi * 16 + (lane & 15)) * 128 +
                                                ks * 32 + (lane >> 4) * 16));
                ldsm_x4(ah[mi], sAh + off);
                ldsm_x4(al[mi], sAl + off);
            }
            uint32_t bh[8], bl[8];
#pragma unroll
            for (int np = 0; np < 2; np++) {
                int g = lane >> 3;
                int nrow = n_base + np * 16 + (lane & 7) + ((g & 2) ? 8 : 0);
                uint32_t off = sw128((uint32_t)(nrow * 128 + ks * 32 + (g & 1) * 16));
                ldsm_x4(&bh[np * 4], sBh + off);
                ldsm_x4(&bl[np * 4], sBl + off);
            }
#pragma unroll
            for (int mi = 0; mi < 2; mi++)
#pragma unroll
                for (int nb = 0; nb < 4; nb++) {
                    const int bo = (nb >> 1) * 4 + (nb & 1) * 2;
                    mma16816(acc[mi][nb], ah[mi], &bh[bo]);
                    mma16816(acc[mi][nb], ah[mi], &bl[bo]);
                    mma16816(acc[mi][nb], al[mi], &bh[bo]);
                }
        }
        __syncthreads();
    }

    float* P = (ntile < 2) ? g_Pi : g_Pj;
    const float* bias = (ntile < 2) ? bi : bj;
    int colbase = (ntile & 1) * 128;
#pragma unroll
    for (int mi = 0; mi < 2; mi++) {
        int mrow0 = m0 + m_base + mi * 16 + (lane >> 2);
#pragma unroll
        for (int nb = 0; nb < 4; nb++) {
            int n = n_base + nb * 8 + 2 * (lane & 3);
            float b0 = bias[colbase + n], b1 = bias[colbase + n + 1];
            if (mrow0 < NN) {
                float2 v = make_float2(acc[mi][nb][0] + b0, acc[mi][nb][1] + b1);
                *(float2*)(P + (size_t)mrow0 * 256 + colbase + n) = v;
            }
            if (mrow0 + 8 < NN) {
                float2 v = make_float2(acc[mi][nb][2] + b0, acc[mi][nb][3] + b1);
                *(float2*)(P + (size_t)(mrow0 + 8) * 256 + colbase + n) = v;
            }
        }
    }
#undef LOAD_STAGE
}

// ---------------- CSR build ----------------
__global__ void hist_kernel(const int* __restrict__ receivers) {
    int e = blockIdx.x * blockDim.x + threadIdx.x;
    if (e < NE) atomicAdd(&g_cnt[receivers[e]], 1);
}

__global__ __launch_bounds__(1024) void scan_kernel() {
    __shared__ int sh[1024];
    const int CH = 49;
    int tid = threadIdx.x;
    int base = tid * CH;
    int s = 0;
    for (int i = 0; i < CH; i++) {
        int idx = base + i;
        if (idx < NN) s += g_cnt[idx];
    }
    sh[tid] = s;
    __syncthreads();
    int incl = s;
    for (int d = 1; d < 1024; d <<= 1) {
        int t = (tid >= d) ? sh[tid - d] : 0;
        __syncthreads();
        incl += t;
        sh[tid] = incl;
        __syncthreads();
    }
    int run = incl - s;
    for (int i = 0; i < CH; i++) {
        int idx = base + i;
        if (idx < NN) {
            int c = g_cnt[idx];
            g_off[idx] = run;
            g_cursor[idx] = run;
            run += c;
        }
    }
    if (tid == 0) g_off[NN] = NE;
}

__global__ void scatter_kernel(const int* __restrict__ senders,
                               const int* __restrict__ receivers) {
    int e = blockIdx.x * blockDim.x + threadIdx.x;
    if (e >= NE) return;
    int r = receivers[e];
    int pos = atomicAdd(&g_cursor[r], 1);
    g_psend[pos] = senders[e];
}

// ---------------- fused edge phase: warp per receiver, ONLINE softmax -------
// Single pass over edges: running max m, running sum s, running accumulator.
// lane owns elements c*128 + lane*4 .. +3 (c=0,1): head0 = lane>>3, head1 = 4+(lane>>3).
// Logit reduction is an 8-lane butterfly within the head group; result (and the
// running max) is uniform across the group, so the rescale branch is non-divergent.
__global__ __launch_bounds__(256) void fused_edge_kernel(
    const float* __restrict__ a_w, float* __restrict__ out)
{
    int wib = threadIdx.x >> 5;
    int lane = threadIdx.x & 31;
    int r = blockIdx.x * 8 + wib;
    if (r >= NN) return;
    int lo = g_off[r];
    int deg = g_off[r + 1] - lo;

    float4 acc0 = make_float4(0.f, 0.f, 0.f, 0.f);
    float4 acc1 = make_float4(0.f, 0.f, 0.f, 0.f);
    float s0 = 0.0f, s1 = 0.0f;
    float m0 = -INFINITY, m1 = -INFINITY;

    if (deg > 0) {
        float4 awv = *(const float4*)(a_w + (lane & 7) * 4);
        const float4* pj4 = (const float4*)(g_Pj + (size_t)r * 256);
        float4 pjv0 = pj4[lane];
        float4 pjv1 = pj4[32 + lane];
        const int* ps = g_psend + lo;

#pragma unroll 2
        for (int j = 0; j < deg; j++) {
            int s = ps[j];
            const float4* pi4 = (const float4*)(g_Pi + (size_t)s * 256);
            float4 v0 = pi4[lane];
            float4 v1 = pi4[32 + lane];
            // logits (a_b cancels in softmax; omitted)
            float p0 = mish1(v0.x + pjv0.x) * awv.x;
            p0 = fmaf(mish1(v0.y + pjv0.y), awv.y, p0);
            p0 = fmaf(mish1(v0.z + pjv0.z), awv.z, p0);
            p0 = fmaf(mish1(v0.w + pjv0.w), awv.w, p0);
            float p1 = mish1(v1.x + pjv1.x) * awv.x;
            p1 = fmaf(mish1(v1.y + pjv1.y), awv.y, p1);
            p1 = fmaf(mish1(v1.z + pjv1.z), awv.z, p1);
            p1 = fmaf(mish1(v1.w + pjv1.w), awv.w, p1);
#pragma unroll
            for (int o = 4; o > 0; o >>= 1) {
                p0 += __shfl_xor_sync(0xffffffffu, p0, o);
                p1 += __shfl_xor_sync(0xffffffffu, p1, o);
            }
            // online softmax update (branch is uniform across the 8-lane group)
            if (p0 > m0) {
                float sc = __expf(m0 - p0);
                s0 *= sc;
                acc0.x *= sc; acc0.y *= sc; acc0.z *= sc; acc0.w *= sc;
                m0 = p0;
            }
            if (p1 > m1) {
                float sc = __expf(m1 - p1);
                s1 *= sc;
                acc1.x *= sc; acc1.y *= sc; acc1.z *= sc; acc1.w *= sc;
                m1 = p1;
            }
            float w0 = __expf(p0 - m0);
            float w1 = __expf(p1 - m1);
            s0 += w0;
            s1 += w1;
            acc0.x = fmaf(v0.x, w0, acc0.x);
            acc0.y = fmaf(v0.y, w0, acc0.y);
            acc0.z = fmaf(v0.z, w0, acc0.z);
            acc0.w = fmaf(v0.w, w0, acc0.w);
            acc1.x = fmaf(v1.x, w1, acc1.x);
            acc1.y = fmaf(v1.y, w1, acc1.y);
            acc1.z = fmaf(v1.z, w1, acc1.z);
            acc1.w = fmaf(v1.w, w1, acc1.w);
        }
        float r0 = 1.0f / s0, r1 = 1.0f / s1;
        acc0.x *= r0; acc0.y *= r0; acc0.z *= r0; acc0.w *= r0;
        acc1.x *= r1; acc1.y *= r1; acc1.z *= r1; acc1.w *= r1;
    }

    float4* o4 = (float4*)(out + (size_t)r * 256);
    o4[lane] = acc0;
    o4[32 + lane] = acc1;
}

// ---------------- launch ----------------
extern "C" void kernel_launch(void* const* d_in, const int* in_sizes, int n_in,
                              void* d_out, int out_size)
{
    const float* nodes     = (const float*)d_in[0];
    const int*   senders   = (const int*)d_in[1];
    const int*   receivers = (const int*)d_in[2];
    const float* Wi        = (const float*)d_in[3];
    const float* bi        = (const float*)d_in[4];
    const float* Wj        = (const float*)d_in[5];
    const float* bj        = (const float*)d_in[6];
    const float* a_w       = (const float*)d_in[7];
    float* out = (float*)d_out;

    static bool attr_set = false;
    if (!attr_set) {
        cudaFuncSetAttribute(gemm_mma, cudaFuncAttributeMaxDynamicSharedMemorySize, 132096);
        attr_set = true;
    }

    init_kernel<<<(NN + 255) / 256, 256>>>();

    presplit_nodes<<<(NN * DIN / 8 + 255) / 256, 256>>>(nodes);
    presplit_W<<<(512 * 256 + 255) / 256, 256>>>(Wi, Wj);

    dim3 gg(4, (NN + 127) / 128);
    gemm_mma<<<gg, 512, 132096>>>(bi, bj);

    hist_kernel<<<(NE + 255) / 256, 256>>>(receivers);
    scan_kernel<<<1, 1024>>>();
    scatter_kernel<<<(NE + 255) / 256, 256>>>(senders, receivers);

    fused_edge_kernel<<<(NN + 7) / 8, 256>>>(a_w, out);
}

// round 7
// speedup vs baseline: 1.4300x; 1.4300x over previous
#include <cuda_runtime.h>
#include <cuda_bf16.h>
#include <cstdint>
#include <math.h>

#define NN 50000
#define NE 400000
#define DIN 256
#define EMB 256
#define NH 8
#define HD 32

// ---------------- scratch (device globals; no runtime alloc) ----------------
__device__ __align__(16) float    g_Pi[(size_t)NN * EMB];
__device__ __align__(16) float    g_Pj[(size_t)NN * EMB];
__device__ __align__(16) float    g_spill[(size_t)NE * NH];    // rare deg>32 spill

// CSR
__device__ int g_cnt[NN];
__device__ int g_off[NN + 1];
__device__ int g_cursor[NN];
__device__ int g_psend[NE];    // sender of perm-ordered edge

// split-bf16 operands for tensor-core GEMM
__device__ __align__(16) __nv_bfloat16 g_Ahi[(size_t)NN * DIN];
__device__ __align__(16) __nv_bfloat16 g_Alo[(size_t)NN * DIN];
__device__ __align__(16) __nv_bfloat16 g_Bhi[(size_t)512 * DIN];  // [n_global][k]
__device__ __align__(16) __nv_bfloat16 g_Blo[(size_t)512 * DIN];

// ---------------- helpers ----------------
__device__ __forceinline__ uint32_t smem_u32(const void* p) {
    uint32_t a;
    asm("{ .reg .u64 t; cvta.to.shared.u64 t, %1; cvt.u32.u64 %0, t; }" : "=r"(a) : "l"(p));
    return a;
}
__device__ __forceinline__ uint32_t sw128(uint32_t off) { return off ^ ((off >> 3) & 0x70); }

__device__ __forceinline__ void ldsm_x4(uint32_t* r, uint32_t addr) {
    asm volatile("ldmatrix.sync.aligned.m8n8.x4.shared.b16 {%0,%1,%2,%3}, [%4];"
                 : "=r"(r[0]), "=r"(r[1]), "=r"(r[2]), "=r"(r[3]) : "r"(addr));
}
__device__ __forceinline__ void mma16816(float* c, const uint32_t* a, const uint32_t* b) {
    asm volatile("mma.sync.aligned.m16n8k16.row.col.f32.bf16.bf16.f32 "
                 "{%0,%1,%2,%3}, {%4,%5,%6,%7}, {%8,%9}, {%0,%1,%2,%3};"
                 : "+f"(c[0]), "+f"(c[1]), "+f"(c[2]), "+f"(c[3])
                 : "r"(a[0]), "r"(a[1]), "r"(a[2]), "r"(a[3]), "r"(b[0]), "r"(b[1]));
}
__device__ __forceinline__ void cp_async16(uint32_t dst, const void* src) {
    asm volatile("cp.async.cg.shared.global [%0], [%1], 16;" :: "r"(dst), "l"(src));
}
#define CP_COMMIT() asm volatile("cp.async.commit_group;" ::: "memory")
#define CP_WAIT(n)  asm volatile("cp.async.wait_group %0;" :: "n"(n) : "memory")

// mish(x) = x * tanh(softplus(x)) = x * (t^2 + 2t) / (t^2 + 2t + 2),  t = e^x
__device__ __forceinline__ float mish1(float x) {
    if (x > 20.0f) return x;
    float t = __expf(x);
    float u = fmaf(t, t, t + t);
    return x * __fdividef(u, u + 2.0f);
}

// ---------------- init: zero CSR counters ----------------
__global__ void init_kernel() {
    int i = blockIdx.x * blockDim.x + threadIdx.x;
    if (i < NN) g_cnt[i] = 0;
}

// ---------------- pre-split nodes into bf16 hi/lo ----------------
__global__ __launch_bounds__(256) void presplit_nodes(const float* __restrict__ nodes) {
    size_t i = (size_t)blockIdx.x * blockDim.x + threadIdx.x;   // unit of 8 floats
    size_t total = (size_t)NN * DIN / 8;
    if (i >= total) return;
    const float4* src = (const float4*)nodes + i * 2;
    float4 v0 = src[0], v1 = src[1];
    float f[8] = {v0.x, v0.y, v0.z, v0.w, v1.x, v1.y, v1.z, v1.w};
    alignas(16) __nv_bfloat16 h[8];
    alignas(16) __nv_bfloat16 l[8];
#pragma unroll
    for (int j = 0; j < 8; j++) {
        h[j] = __float2bfloat16(f[j]);
        l[j] = __float2bfloat16(f[j] - __bfloat162float(h[j]));
    }
    *(uint4*)(g_Ahi + i * 8) = *(uint4*)h;
    *(uint4*)(g_Alo + i * 8) = *(uint4*)l;
}

// ---------------- pre-split + transpose W into [n][k] bf16 hi/lo ----------------
__global__ __launch_bounds__(256) void presplit_W(const float* __restrict__ Wi,
                                                  const float* __restrict__ Wj) {
    int idx = blockIdx.x * blockDim.x + threadIdx.x;
    if (idx >= 512 * 256) return;
    int n = idx >> 8, k = idx & 255;
    const float* W = (n < 256) ? Wi : Wj;
    int col = n & 255;
    float x = W[(size_t)k * 256 + col];
    __nv_bfloat16 h = __float2bfloat16(x);
    __nv_bfloat16 l = __float2bfloat16(x - __bfloat162float(h));
    g_Bhi[(size_t)n * 256 + k] = h;
    g_Blo[(size_t)n * 256 + k] = l;
}

// ---------------- tensor-core projection GEMM, 3-stage cp.async pipeline ----
__global__ __launch_bounds__(512) void gemm_mma(const float* __restrict__ bi,
                                                const float* __restrict__ bj) {
    extern __shared__ char dsm[];
    uint32_t base = (smem_u32(dsm) + 1023) & ~1023u;

    int tid = threadIdx.x, wid = tid >> 5, lane = tid & 31;
    int warp_m = wid & 3, warp_n = wid >> 2;
    int m_base = warp_m * 32, n_base = warp_n * 32;
    int ntile = blockIdx.x;
    int m0 = blockIdx.y * 128;
    size_t brow0 = (size_t)ntile * 128 * 256;

    float acc[2][4][4];
#pragma unroll
    for (int i = 0; i < 2; i++)
#pragma unroll
        for (int j = 0; j < 4; j++)
#pragma unroll
            for (int q = 0; q < 4; q++) acc[i][j][q] = 0.0f;

#define LOAD_STAGE(sbuf, kc_) do {                                         \
    uint32_t sAh_ = (sbuf), sAl_ = (sbuf) + 16384,                          \
             sBh_ = (sbuf) + 32768, sBl_ = (sbuf) + 49152;                  \
    int k0_ = (kc_) * 64;                                                   \
    _Pragma("unroll")                                                       \
    for (int u = tid; u < 1024; u += 512) {                                 \
        int r_ = u >> 3, g_ = u & 7;                                        \
        uint32_t off_ = sw128((uint32_t)(r_ * 128 + g_ * 16));              \
        int row_ = m0 + r_; if (row_ > NN - 1) row_ = NN - 1;               \
        size_t sa_ = (size_t)row_ * 256 + k0_ + g_ * 8;                     \
        cp_async16(sAh_ + off_, g_Ahi + sa_);                               \
        cp_async16(sAl_ + off_, g_Alo + sa_);                               \
        size_t sb_ = brow0 + (size_t)r_ * 256 + k0_ + g_ * 8;               \
        cp_async16(sBh_ + off_, g_Bhi + sb_);                               \
        cp_async16(sBl_ + off_, g_Blo + sb_);                               \
    }                                                                       \
} while (0)

    LOAD_STAGE(base, 0);
    CP_COMMIT();
    LOAD_STAGE(base + 65536u, 1);
    CP_COMMIT();

#pragma unroll
    for (int kc = 0; kc < 4; kc++) {
        if (kc < 3) { CP_WAIT(1); } else { CP_WAIT(0); }
        __syncthreads();
        // safe to refill buffer (kc+2)%3 == (kc-1)%3: all warps passed MMA kc-1
        if (kc + 2 < 4) {
            LOAD_STAGE(base + (uint32_t)((kc + 2) % 3) * 65536u, kc + 2);
            CP_COMMIT();
        }
        uint32_t cur = base + (uint32_t)(kc % 3) * 65536u;
        uint32_t sAh = cur, sAl = cur + 16384, sBh = cur + 32768, sBl = cur + 49152;
#pragma unroll
        for (int ks = 0; ks < 4; ks++) {
            uint32_t ah[2][4], al[2][4];
#pragma unroll
            for (int mi = 0; mi < 2; mi++) {
                uint32_t off = sw128((uint32_t)((m_base + mi * 16 + (lane & 15)) * 128 +
                                                ks * 32 + (lane >> 4) * 16));
                ldsm_x4(ah[mi], sAh + off);
                ldsm_x4(al[mi], sAl + off);
            }
            uint32_t bh[8], bl[8];
#pragma unroll
            for (int np = 0; np < 2; np++) {
                int g = lane >> 3;
                int nrow = n_base + np * 16 + (lane & 7) + ((g & 2) ? 8 : 0);
                uint32_t off = sw128((uint32_t)(nrow * 128 + ks * 32 + (g & 1) * 16));
                ldsm_x4(&bh[np * 4], sBh + off);
                ldsm_x4(&bl[np * 4], sBl + off);
            }
#pragma unroll
            for (int mi = 0; mi < 2; mi++)
#pragma unroll
                for (int nb = 0; nb < 4; nb++) {
                    const int bo = (nb >> 1) * 4 + (nb & 1) * 2;
                    mma16816(acc[mi][nb], ah[mi], &bh[bo]);
                    mma16816(acc[mi][nb], ah[mi], &bl[bo]);
                    mma16816(acc[mi][nb], al[mi], &bh[bo]);
                }
        }
    }

    float* P = (ntile < 2) ? g_Pi : g_Pj;
    const float* bias = (ntile < 2) ? bi : bj;
    int colbase = (ntile & 1) * 128;
#pragma unroll
    for (int mi = 0; mi < 2; mi++) {
        int mrow0 = m0 + m_base + mi * 16 + (lane >> 2);
#pragma unroll
        for (int nb = 0; nb < 4; nb++) {
            int n = n_base + nb * 8 + 2 * (lane & 3);
            float b0 = bias[colbase + n], b1 = bias[colbase + n + 1];
            if (mrow0 < NN) {
                float2 v = make_float2(acc[mi][nb][0] + b0, acc[mi][nb][1] + b1);
                *(float2*)(P + (size_t)mrow0 * 256 + colbase + n) = v;
            }
            if (mrow0 + 8 < NN) {
                float2 v = make_float2(acc[mi][nb][2] + b0, acc[mi][nb][3] + b1);
                *(float2*)(P + (size_t)(mrow0 + 8) * 256 + colbase + n) = v;
            }
        }
    }
#undef LOAD_STAGE
}

// ---------------- CSR build ----------------
__global__ void hist_kernel(const int* __restrict__ receivers) {
    int e = blockIdx.x * blockDim.x + threadIdx.x;
    if (e < NE) atomicAdd(&g_cnt[receivers[e]], 1);
}

__global__ __launch_bounds__(1024) void scan_kernel() {
    __shared__ int sh[1024];
    const int CH = 49;
    int tid = threadIdx.x;
    int base = tid * CH;
    int s = 0;
    for (int i = 0; i < CH; i++) {
        int idx = base + i;
        if (idx < NN) s += g_cnt[idx];
    }
    sh[tid] = s;
    __syncthreads();
    int incl = s;
    for (int d = 1; d < 1024; d <<= 1) {
        int t = (tid >= d) ? sh[tid - d] : 0;
        __syncthreads();
        incl += t;
        sh[tid] = incl;
        __syncthreads();
    }
    int run = incl - s;
    for (int i = 0; i < CH; i++) {
        int idx = base + i;
        if (idx < NN) {
            int c = g_cnt[idx];
            g_off[idx] = run;
            g_cursor[idx] = run;
            run += c;
        }
    }
    if (tid == 0) g_off[NN] = NE;
}

__global__ void scatter_kernel(const int* __restrict__ senders,
                               const int* __restrict__ receivers) {
    int e = blockIdx.x * blockDim.x + threadIdx.x;
    if (e >= NE) return;
    int r = receivers[e];
    int pos = atomicAdd(&g_cursor[r], 1);
    g_psend[pos] = senders[e];
}

// ---------------- fused edge phase: warp per receiver, TWO-PASS --------------
// lane owns elements c*128 + lane*4 .. +3 (c=0,1): head0 = lane>>3, head1 = 4+(lane>>3).
__global__ __launch_bounds__(256) void fused_edge_kernel(
    const float* __restrict__ a_w, float* __restrict__ out)
{
    __shared__ float s_w[8][32 * NH];
    int wib = threadIdx.x >> 5;
    int lane = threadIdx.x & 31;
    int r = blockIdx.x * 8 + wib;
    if (r >= NN) return;
    int lo = g_off[r];
    int deg = g_off[r + 1] - lo;

    float4 acc0 = make_float4(0.f, 0.f, 0.f, 0.f);
    float4 acc1 = make_float4(0.f, 0.f, 0.f, 0.f);

    if (deg > 0) {
        float4 awv = *(const float4*)(a_w + (lane & 7) * 4);
        const float4* pj4 = (const float4*)(g_Pj + (size_t)r * 256);
        float4 pjv0 = pj4[lane];
        float4 pjv1 = pj4[32 + lane];
        float* wbuf = (deg <= 32) ? s_w[wib] : (g_spill + (size_t)lo * NH);

        int hgrp = lane >> 3;               // 0..3
        bool writer = (lane & 7) == 0;
        const int* ps = g_psend + lo;

        // ---- pass 1: logits (a_b cancels in softmax; omitted) ----
#pragma unroll 2
        for (int j = 0; j < deg; j++) {
            int s = ps[j];
            const float4* pi4 = (const float4*)(g_Pi + (size_t)s * 256);
            float4 v0 = pi4[lane];
            float4 v1 = pi4[32 + lane];
            float p0 = mish1(v0.x + pjv0.x) * awv.x;
            p0 = fmaf(mish1(v0.y + pjv0.y), awv.y, p0);
            p0 = fmaf(mish1(v0.z + pjv0.z), awv.z, p0);
            p0 = fmaf(mish1(v0.w + pjv0.w), awv.w, p0);
            float p1 = mish1(v1.x + pjv1.x) * awv.x;
            p1 = fmaf(mish1(v1.y + pjv1.y), awv.y, p1);
            p1 = fmaf(mish1(v1.z + pjv1.z), awv.z, p1);
            p1 = fmaf(mish1(v1.w + pjv1.w), awv.w, p1);
#pragma unroll
            for (int o = 4; o > 0; o >>= 1) {
                p0 += __shfl_xor_sync(0xffffffffu, p0, o);
                p1 += __shfl_xor_sync(0xffffffffu, p1, o);
            }
            if (writer) {
                wbuf[j * NH + hgrp] = p0;
                wbuf[j * NH + 4 + hgrp] = p1;
            }
        }
        __syncwarp();

        // ---- softmax over this receiver's edges ----
        {
            int h = lane >> 2;       // head 0..7
            int e0 = lane & 3;       // edge stripe
            float mx = -INFINITY;
            for (int j = e0; j < deg; j += 4) mx = fmaxf(mx, wbuf[j * NH + h]);
            mx = fmaxf(mx, __shfl_xor_sync(0xffffffffu, mx, 1));
            mx = fmaxf(mx, __shfl_xor_sync(0xffffffffu, mx, 2));
            float sm = 0.0f;
            for (int j = e0; j < deg; j += 4) {
                float e = __expf(wbuf[j * NH + h] - mx);
                wbuf[j * NH + h] = e;
                sm += e;
            }
            sm += __shfl_xor_sync(0xffffffffu, sm, 1);
            sm += __shfl_xor_sync(0xffffffffu, sm, 2);
            float dinv = 1.0f / sm;
            for (int j = e0; j < deg; j += 4) wbuf[j * NH + h] *= dinv;
        }
        __syncwarp();

        // ---- pass 2: weighted aggregation ----
#pragma unroll 2
        for (int j = 0; j < deg; j++) {
            int s = ps[j];
            const float4* pi4 = (const float4*)(g_Pi + (size_t)s * 256);
            float4 v0 = pi4[lane];
            float4 v1 = pi4[32 + lane];
            float w0 = wbuf[j * NH + hgrp];
            float w1 = wbuf[j * NH + 4 + hgrp];
            acc0.x = fmaf(v0.x, w0, acc0.x);
            acc0.y = fmaf(v0.y, w0, acc0.y);
            acc0.z = fmaf(v0.z, w0, acc0.z);
            acc0.w = fmaf(v0.w, w0, acc0.w);
            acc1.x = fmaf(v1.x, w1, acc1.x);
            acc1.y = fmaf(v1.y, w1, acc1.y);
            acc1.z = fmaf(v1.z, w1, acc1.z);
            acc1.w = fmaf(v1.w, w1, acc1.w);
        }
    }

    float4* o4 = (float4*)(out + (size_t)r * 256);
    o4[lane] = acc0;
    o4[32 + lane] = acc1;
}

// ---------------- launch ----------------
extern "C" void kernel_launch(void* const* d_in, const int* in_sizes, int n_in,
                              void* d_out, int out_size)
{
    const float* nodes     = (const float*)d_in[0];
    const int*   senders   = (const int*)d_in[1];
    const int*   receivers = (const int*)d_in[2];
    const float* Wi        = (const float*)d_in[3];
    const float* bi        = (const float*)d_in[4];
    const float* Wj        = (const float*)d_in[5];
    const float* bj        = (const float*)d_in[6];
    const float* a_w       = (const float*)d_in[7];
    float* out = (float*)d_out;

    static cudaStream_t s2 = nullptr;
    static cudaEvent_t evF = nullptr, evJ = nullptr;
    if (!s2) {
        cudaFuncSetAttribute(gemm_mma, cudaFuncAttributeMaxDynamicSharedMemorySize, 197632);
        cudaStreamCreateWithFlags(&s2, cudaStreamNonBlocking);
        cudaEventCreateWithFlags(&evF, cudaEventDisableTiming);
        cudaEventCreateWithFlags(&evJ, cudaEventDisableTiming);
    }

    // fork: CSR build on side stream, overlapped with presplit + GEMM
    cudaEventRecord(evF, 0);
    cudaStreamWaitEvent(s2, evF, 0);
    init_kernel<<<(NN + 255) / 256, 256, 0, s2>>>();
    hist_kernel<<<(NE + 255) / 256, 256, 0, s2>>>(receivers);
    scan_kernel<<<1, 1024, 0, s2>>>();
    scatter_kernel<<<(NE + 255) / 256, 256, 0, s2>>>(senders, receivers);
    cudaEventRecord(evJ, s2);

    // main stream: projection pipeline
    presplit_nodes<<<(NN * DIN / 8 + 255) / 256, 256>>>(nodes);
    presplit_W<<<(512 * 256 + 255) / 256, 256>>>(Wi, Wj);

    dim3 gg(4, (NN + 127) / 128);
    gemm_mma<<<gg, 512, 197632>>>(bi, bj);

    // join, then fused edge phase
    cudaStreamWaitEvent(0, evJ, 0);
    fused_edge_kernel<<<(NN + 7) / 8, 256>>>(a_w, out);
}

// round 8
// speedup vs baseline: 1.4302x; 1.0001x over previous
#include <cuda_runtime.h>
#include <cuda_fp16.h>
#include <cstdint>
#include <math.h>

#define NN 50000
#define NE 400000
#define DIN 256
#define EMB 256
#define NH 8
#define HD 32

// ---------------- scratch (device globals; no runtime alloc) ----------------
__device__ __align__(16) float    g_Pi[(size_t)NN * EMB];
__device__ __align__(16) float    g_Pj[(size_t)NN * EMB];
__device__ __align__(16) float    g_spill[(size_t)NE * NH];    // rare deg>32 spill

// CSR
__device__ int g_cnt[NN];
__device__ int g_off[NN + 1];
__device__ int g_cursor[NN];
__device__ int g_psend[NE];    // sender of perm-ordered edge

// split-fp16 operands for tensor-core GEMM (2-term: AhBh + AhBl)
__device__ __align__(16) __half g_Ah[(size_t)NN * DIN];
__device__ __align__(16) __half g_Bh[(size_t)512 * DIN];   // [n_global][k]
__device__ __align__(16) __half g_Bl[(size_t)512 * DIN];

// ---------------- helpers ----------------
__device__ __forceinline__ uint32_t smem_u32(const void* p) {
    uint32_t a;
    asm("{ .reg .u64 t; cvta.to.shared.u64 t, %1; cvt.u32.u64 %0, t; }" : "=r"(a) : "l"(p));
    return a;
}
__device__ __forceinline__ uint32_t sw128(uint32_t off) { return off ^ ((off >> 3) & 0x70); }

__device__ __forceinline__ void ldsm_x4(uint32_t* r, uint32_t addr) {
    asm volatile("ldmatrix.sync.aligned.m8n8.x4.shared.b16 {%0,%1,%2,%3}, [%4];"
                 : "=r"(r[0]), "=r"(r[1]), "=r"(r[2]), "=r"(r[3]) : "r"(addr));
}
__device__ __forceinline__ void mma16816(float* c, const uint32_t* a, const uint32_t* b) {
    asm volatile("mma.sync.aligned.m16n8k16.row.col.f32.f16.f16.f32 "
                 "{%0,%1,%2,%3}, {%4,%5,%6,%7}, {%8,%9}, {%0,%1,%2,%3};"
                 : "+f"(c[0]), "+f"(c[1]), "+f"(c[2]), "+f"(c[3])
                 : "r"(a[0]), "r"(a[1]), "r"(a[2]), "r"(a[3]), "r"(b[0]), "r"(b[1]));
}
__device__ __forceinline__ void cp_async16(uint32_t dst, const void* src) {
    asm volatile("cp.async.cg.shared.global [%0], [%1], 16;" :: "r"(dst), "l"(src));
}
#define CP_COMMIT() asm volatile("cp.async.commit_group;" ::: "memory")
#define CP_WAIT(n)  asm volatile("cp.async.wait_group %0;" :: "n"(n) : "memory")

// mish(x) = x * tanh(softplus(x)) = x * (t^2 + 2t) / (t^2 + 2t + 2),  t = e^x
__device__ __forceinline__ float mish1(float x) {
    if (x > 20.0f) return x;
    float t = __expf(x);
    float u = fmaf(t, t, t + t);
    return x * __fdividef(u, u + 2.0f);
}

// ---------------- init: zero CSR counters ----------------
__global__ void init_kernel() {
    int i = blockIdx.x * blockDim.x + threadIdx.x;
    if (i < NN) g_cnt[i] = 0;
}

// ---------------- pre-split nodes into fp16 hi (lo term dropped) -------------
__global__ __launch_bounds__(256) void presplit_nodes(const float* __restrict__ nodes) {
    size_t i = (size_t)blockIdx.x * blockDim.x + threadIdx.x;   // unit of 8 floats
    size_t total = (size_t)NN * DIN / 8;
    if (i >= total) return;
    const float4* src = (const float4*)nodes + i * 2;
    float4 v0 = src[0], v1 = src[1];
    float f[8] = {v0.x, v0.y, v0.z, v0.w, v1.x, v1.y, v1.z, v1.w};
    alignas(16) __half h[8];
#pragma unroll
    for (int j = 0; j < 8; j++) h[j] = __float2half(f[j]);
    *(uint4*)(g_Ah + i * 8) = *(uint4*)h;
}

// ---------------- pre-split + transpose W into [n][k] fp16 hi/lo -------------
__global__ __launch_bounds__(256) void presplit_W(const float* __restrict__ Wi,
                                                  const float* __restrict__ Wj) {
    int idx = blockIdx.x * blockDim.x + threadIdx.x;
    if (idx >= 512 * 256) return;
    int n = idx >> 8, k = idx & 255;
    const float* W = (n < 256) ? Wi : Wj;
    int col = n & 255;
    float x = W[(size_t)k * 256 + col];
    __half h = __float2half(x);
    __half l = __float2half(x - __half2float(h));
    g_Bh[(size_t)n * 256 + k] = h;
    g_Bl[(size_t)n * 256 + k] = l;
}

// ---------------- tensor-core projection GEMM, 3-stage cp.async pipeline ----
// P = Ah*Bh + Ah*Bl  (fp16 split, fp32 accum)
__global__ __launch_bounds__(512) void gemm_mma(const float* __restrict__ bi,
                                                const float* __restrict__ bj) {
    extern __shared__ char dsm[];
    uint32_t base = (smem_u32(dsm) + 1023) & ~1023u;
    const uint32_t STG = 49152u;   // 3 x 16KB tiles per stage

    int tid = threadIdx.x, wid = tid >> 5, lane = tid & 31;
    int warp_m = wid & 3, warp_n = wid >> 2;
    int m_base = warp_m * 32, n_base = warp_n * 32;
    int ntile = blockIdx.x;
    int m0 = blockIdx.y * 128;
    size_t brow0 = (size_t)ntile * 128 * 256;

    float acc[2][4][4];
#pragma unroll
    for (int i = 0; i < 2; i++)
#pragma unroll
        for (int j = 0; j < 4; j++)
#pragma unroll
            for (int q = 0; q < 4; q++) acc[i][j][q] = 0.0f;

#define LOAD_STAGE(sbuf, kc_) do {                                         \
    uint32_t sA_ = (sbuf), sBh_ = (sbuf) + 16384, sBl_ = (sbuf) + 32768;    \
    int k0_ = (kc_) * 64;                                                   \
    _Pragma("unroll")                                                       \
    for (int u = tid; u < 1024; u += 512) {                                 \
        int r_ = u >> 3, g_ = u & 7;                                        \
        uint32_t off_ = sw128((uint32_t)(r_ * 128 + g_ * 16));              \
        if (u < 512) { /* B tiles: r_=0..63 covers rows via two halves */   \
            size_t sb_ = brow0 + (size_t)(r_) * 256 + k0_ + g_ * 8;         \
            cp_async16(sBh_ + off_, g_Bh + sb_);                            \
            cp_async16(sBl_ + off_, g_Bl + sb_);                            \
            size_t sb2_ = brow0 + (size_t)(r_ + 64) * 256 + k0_ + g_ * 8;   \
            uint32_t off2_ = sw128((uint32_t)((r_ + 64) * 128 + g_ * 16));  \
            cp_async16(sBh_ + off2_, g_Bh + sb2_);                          \
            cp_async16(sBl_ + off2_, g_Bl + sb2_);                          \
        }                                                                   \
        int row_ = m0 + r_; if (row_ > NN - 1) row_ = NN - 1;               \
        size_t sa_ = (size_t)row_ * 256 + k0_ + g_ * 8;                     \
        cp_async16(sA_ + off_, g_Ah + sa_);                                 \
    }                                                                       \
} while (0)

    LOAD_STAGE(base, 0);
    CP_COMMIT();
    LOAD_STAGE(base + STG, 1);
    CP_COMMIT();

#pragma unroll
    for (int kc = 0; kc < 4; kc++) {
        if (kc < 3) { CP_WAIT(1); } else { CP_WAIT(0); }
        __syncthreads();
        if (kc + 2 < 4) {
            LOAD_STAGE(base + (uint32_t)((kc + 2) % 3) * STG, kc + 2);
            CP_COMMIT();
        }
        uint32_t cur = base + (uint32_t)(kc % 3) * STG;
        uint32_t sA = cur, sBh = cur + 16384, sBl = cur + 32768;
#pragma unroll
        for (int ks = 0; ks < 4; ks++) {
            uint32_t ah[2][4];
#pragma unroll
            for (int mi = 0; mi < 2; mi++) {
                uint32_t off = sw128((uint32_t)((m_base + mi * 16 + (lane & 15)) * 128 +
                                                ks * 32 + (lane >> 4) * 16));
                ldsm_x4(ah[mi], sA + off);
            }
            uint32_t bh[8], bl[8];
#pragma unroll
            for (int np = 0; np < 2; np++) {
                int g = lane >> 3;
                int nrow = n_base + np * 16 + (lane & 7) + ((g & 2) ? 8 : 0);
                uint32_t off = sw128((uint32_t)(nrow * 128 + ks * 32 + (g & 1) * 16));
                ldsm_x4(&bh[np * 4], sBh + off);
                ldsm_x4(&bl[np * 4], sBl + off);
            }
#pragma unroll
            for (int mi = 0; mi < 2; mi++)
#pragma unroll
                for (int nb = 0; nb < 4; nb++) {
                    const int bo = (nb >> 1) * 4 + (nb & 1) * 2;
                    mma16816(acc[mi][nb], ah[mi], &bh[bo]);
                    mma16816(acc[mi][nb], ah[mi], &bl[bo]);
                }
        }
    }

    float* P = (ntile < 2) ? g_Pi : g_Pj;
    const float* bias = (ntile < 2) ? bi : bj;
    int colbase = (ntile & 1) * 128;
#pragma unroll
    for (int mi = 0; mi < 2; mi++) {
        int mrow0 = m0 + m_base + mi * 16 + (lane >> 2);
#pragma unroll
        for (int nb = 0; nb < 4; nb++) {
            int n = n_base + nb * 8 + 2 * (lane & 3);
            float b0 = bias[colbase + n], b1 = bias[colbase + n + 1];
            if (mrow0 < NN) {
                float2 v = make_float2(acc[mi][nb][0] + b0, acc[mi][nb][1] + b1);
                *(float2*)(P + (size_t)mrow0 * 256 + colbase + n) = v;
            }
            if (mrow0 + 8 < NN) {
                float2 v = make_float2(acc[mi][nb][2] + b0, acc[mi][nb][3] + b1);
                *(float2*)(P + (size_t)(mrow0 + 8) * 256 + colbase + n) = v;
            }
        }
    }
#undef LOAD_STAGE
}

// ---------------- CSR build ----------------
__global__ void hist_kernel(const int* __restrict__ receivers) {
    int e = blockIdx.x * blockDim.x + threadIdx.x;
    if (e < NE) atomicAdd(&g_cnt[receivers[e]], 1);
}

__global__ __launch_bounds__(1024) void scan_kernel() {
    __shared__ int sh[1024];
    const int CH = 49;
    int tid = threadIdx.x;
    int base = tid * CH;
    int s = 0;
    for (int i = 0; i < CH; i++) {
        int idx = base + i;
        if (idx < NN) s += g_cnt[idx];
    }
    sh[tid] = s;
    __syncthreads();
    int incl = s;
    for (int d = 1; d < 1024; d <<= 1) {
        int t = (tid >= d) ? sh[tid - d] : 0;
        __syncthreads();
        incl += t;
        sh[tid] = incl;
        __syncthreads();
    }
    int run = incl - s;
    for (int i = 0; i < CH; i++) {
        int idx = base + i;
        if (idx < NN) {
            int c = g_cnt[idx];
            g_off[idx] = run;
            g_cursor[idx] = run;
            run += c;
        }
    }
    if (tid == 0) g_off[NN] = NE;
}

__global__ void scatter_kernel(const int* __restrict__ senders,
                               const int* __restrict__ receivers) {
    int e = blockIdx.x * blockDim.x + threadIdx.x;
    if (e >= NE) return;
    int r = receivers[e];
    int pos = atomicAdd(&g_cursor[r], 1);
    g_psend[pos] = senders[e];
}

// ---------------- fused edge phase: warp per receiver, TWO-PASS + prefetch ---
__global__ __launch_bounds__(256) void fused_edge_kernel(
    const float* __restrict__ a_w, float* __restrict__ out)
{
    __shared__ float s_w[8][32 * NH];
    int wib = threadIdx.x >> 5;
    int lane = threadIdx.x & 31;
    int r = blockIdx.x * 8 + wib;
    if (r >= NN) return;
    int lo = g_off[r];
    int deg = g_off[r + 1] - lo;

    float4 acc0 = make_float4(0.f, 0.f, 0.f, 0.f);
    float4 acc1 = make_float4(0.f, 0.f, 0.f, 0.f);

    if (deg > 0) {
        float4 awv = *(const float4*)(a_w + (lane & 7) * 4);
        const float4* pj4 = (const float4*)(g_Pj + (size_t)r * 256);
        float4 pjv0 = pj4[lane];
        float4 pjv1 = pj4[32 + lane];
        float* wbuf = (deg <= 32) ? s_w[wib] : (g_spill + (size_t)lo * NH);

        int hgrp = lane >> 3;               // 0..3
        bool writer = (lane & 7) == 0;
        const int* ps = g_psend + lo;

        // ---- pass 1: logits (a_b cancels in softmax; omitted) ----
        {
            const float4* pi4 = (const float4*)(g_Pi + (size_t)ps[0] * 256);
            float4 v0 = pi4[lane];
            float4 v1 = pi4[32 + lane];
            for (int j = 0; j < deg; j++) {
                // prefetch next edge's row before the dependent math chain
                const float4* pn = (const float4*)(
                    g_Pi + (size_t)ps[(j + 1 < deg) ? j + 1 : j] * 256);
                float4 nv0 = pn[lane];
                float4 nv1 = pn[32 + lane];

                float p0 = mish1(v0.x + pjv0.x) * awv.x;
                p0 = fmaf(mish1(v0.y + pjv0.y), awv.y, p0);
                p0 = fmaf(mish1(v0.z + pjv0.z), awv.z, p0);
                p0 = fmaf(mish1(v0.w + pjv0.w), awv.w, p0);
                float p1 = mish1(v1.x + pjv1.x) * awv.x;
                p1 = fmaf(mish1(v1.y + pjv1.y), awv.y, p1);
                p1 = fmaf(mish1(v1.z + pjv1.z), awv.z, p1);
                p1 = fmaf(mish1(v1.w + pjv1.w), awv.w, p1);
#pragma unroll
                for (int o = 4; o > 0; o >>= 1) {
                    p0 += __shfl_xor_sync(0xffffffffu, p0, o);
                    p1 += __shfl_xor_sync(0xffffffffu, p1, o);
                }
                if (writer) {
                    wbuf[j * NH + hgrp] = p0;
                    wbuf[j * NH + 4 + hgrp] = p1;
                }
                v0 = nv0;
                v1 = nv1;
            }
        }
        __syncwarp();

        // ---- softmax over this receiver's edges ----
        {
            int h = lane >> 2;       // head 0..7
            int e0 = lane & 3;       // edge stripe
            float mx = -INFINITY;
            for (int j = e0; j < deg; j += 4) mx = fmaxf(mx, wbuf[j * NH + h]);
            mx = fmaxf(mx, __shfl_xor_sync(0xffffffffu, mx, 1));
            mx = fmaxf(mx, __shfl_xor_sync(0xffffffffu, mx, 2));
            float sm = 0.0f;
            for (int j = e0; j < deg; j += 4) {
                float e = __expf(wbuf[j * NH + h] - mx);
                wbuf[j * NH + h] = e;
                sm += e;
            }
            sm += __shfl_xor_sync(0xffffffffu, sm, 1);
            sm += __shfl_xor_sync(0xffffffffu, sm, 2);
            float dinv = 1.0f / sm;
            for (int j = e0; j < deg; j += 4) wbuf[j * NH + h] *= dinv;
        }
        __syncwarp();

        // ---- pass 2: weighted aggregation (prefetched) ----
        {
            const float4* pi4 = (const float4*)(g_Pi + (size_t)ps[0] * 256);
            float4 v0 = pi4[lane];
            float4 v1 = pi4[32 + lane];
            for (int j = 0; j < deg; j++) {
                const float4* pn = (const float4*)(
                    g_Pi + (size_t)ps[(j + 1 < deg) ? j + 1 : j] * 256);
                float4 nv0 = pn[lane];
                float4 nv1 = pn[32 + lane];
                float w0 = wbuf[j * NH + hgrp];
                float w1 = wbuf[j * NH + 4 + hgrp];
                acc0.x = fmaf(v0.x, w0, acc0.x);
                acc0.y = fmaf(v0.y, w0, acc0.y);
                acc0.z = fmaf(v0.z, w0, acc0.z);
                acc0.w = fmaf(v0.w, w0, acc0.w);
                acc1.x = fmaf(v1.x, w1, acc1.x);
                acc1.y = fmaf(v1.y, w1, acc1.y);
                acc1.z = fmaf(v1.z, w1, acc1.z);
                acc1.w = fmaf(v1.w, w1, acc1.w);
                v0 = nv0;
                v1 = nv1;
            }
        }
    }

    float4* o4 = (float4*)(out + (size_t)r * 256);
    o4[lane] = acc0;
    o4[32 + lane] = acc1;
}

// ---------------- launch ----------------
extern "C" void kernel_launch(void* const* d_in, const int* in_sizes, int n_in,
                              void* d_out, int out_size)
{
    const float* nodes     = (const float*)d_in[0];
    const int*   senders   = (const int*)d_in[1];
    const int*   receivers = (const int*)d_in[2];
    const float* Wi        = (const float*)d_in[3];
    const float* bi        = (const float*)d_in[4];
    const float* Wj        = (const float*)d_in[5];
    const float* bj        = (const float*)d_in[6];
    const float* a_w       = (const float*)d_in[7];
    float* out = (float*)d_out;

    static cudaStream_t s2 = nullptr;
    static cudaEvent_t evF = nullptr, evJ = nullptr;
    if (!s2) {
        cudaFuncSetAttribute(gemm_mma, cudaFuncAttributeMaxDynamicSharedMemorySize, 148480);
        cudaStreamCreateWithFlags(&s2, cudaStreamNonBlocking);
        cudaEventCreateWithFlags(&evF, cudaEventDisableTiming);
        cudaEventCreateWithFlags(&evJ, cudaEventDisableTiming);
    }

    // fork: CSR build on side stream, overlapped with presplit + GEMM
    cudaEventRecord(evF, 0);
    cudaStreamWaitEvent(s2, evF, 0);
    init_kernel<<<(NN + 255) / 256, 256, 0, s2>>>();
    hist_kernel<<<(NE + 255) / 256, 256, 0, s2>>>(receivers);
    scan_kernel<<<1, 1024, 0, s2>>>();
    scatter_kernel<<<(NE + 255) / 256, 256, 0, s2>>>(senders, receivers);
    cudaEventRecord(evJ, s2);

    // main stream: projection pipeline
    presplit_nodes<<<(NN * DIN / 8 + 255) / 256, 256>>>(nodes);
    presplit_W<<<(512 * 256 + 255) / 256, 256>>>(Wi, Wj);

    dim3 gg(4, (NN + 127) / 128);
    gemm_mma<<<gg, 512, 148480>>>(bi, bj);

    // join, then fused edge phase
    cudaStreamWaitEvent(0, evJ, 0);
    fused_edge_kernel<<<(NN + 7) / 8, 256>>>(a_w, out);
}